// round 3
// baseline (speedup 1.0000x reference)
#include <cuda_runtime.h>

// GCN collapse: F_in=1 and F_out=1 make both graph convolutions scalar
// propagations. Pipeline:
//   1) deg count over dst (+1 self loop)  -> dinv = rsqrt(deg)
//   2) s[i] = x[i]*dinv[i]; acc1 seeded with s[i] (self loop)
//   3) edge pass: acc1[dst] += s[src]
//   4) agg1 = dinv*acc1; z = sum_f relu(agg1*W1[f]+b1[f])*W2[f]; t = z*dinv;
//      acc2 seeded with t[i]
//   5) edge pass: acc2[dst] += t[src]
//   6) out[i] = dinv*acc2 + b2
//
// edge_index arrives as int32 (harness downcasts int64), shape [2, E] row-major.

#define MAXN 200000

__device__ int   g_deg[MAXN];
__device__ float g_dinv[MAXN];
__device__ float g_s[MAXN];
__device__ float g_acc1[MAXN];
__device__ float g_t[MAXN];
__device__ float g_acc2[MAXN];

// ---------------------------------------------------------------- zero deg
__global__ void k_zero_deg(int n) {
    int i = blockIdx.x * blockDim.x + threadIdx.x;
    if (i < n) g_deg[i] = 0;
}

// ------------------------------------------------------- degree count pass
// 8 edges per thread via two int4 loads.
__global__ void k_deg(const int* __restrict__ dst, int e) {
    int t = blockIdx.x * blockDim.x + threadIdx.x;
    int base = t * 8;
    if (base + 7 < e) {
        int4 a = reinterpret_cast<const int4*>(dst + base)[0];
        int4 b = reinterpret_cast<const int4*>(dst + base)[1];
        atomicAdd(&g_deg[a.x], 1);
        atomicAdd(&g_deg[a.y], 1);
        atomicAdd(&g_deg[a.z], 1);
        atomicAdd(&g_deg[a.w], 1);
        atomicAdd(&g_deg[b.x], 1);
        atomicAdd(&g_deg[b.y], 1);
        atomicAdd(&g_deg[b.z], 1);
        atomicAdd(&g_deg[b.w], 1);
    } else {
        for (int k = base; k < e; k++) atomicAdd(&g_deg[dst[k]], 1);
    }
}

// ------------------------------------------- node pass 1: dinv, s, seed acc1
__global__ void k_node1(const float* __restrict__ x, int n) {
    int i = blockIdx.x * blockDim.x + threadIdx.x;
    if (i < n) {
        float dinv = rsqrtf((float)(g_deg[i] + 1));   // +1 self loop, deg>=1
        g_dinv[i] = dinv;
        float sv = x[i] * dinv;
        g_s[i] = sv;
        g_acc1[i] = sv;    // self-loop contribution; dinv[dst] applied later
    }
}

// --------------------------------------- scalar scatter-add over edges
// PASS=0: acc1[dst] += s[src] ; PASS=1: acc2[dst] += t[src]
template <int PASS>
__global__ void k_edge(const int* __restrict__ src,
                       const int* __restrict__ dst, int e) {
    const float* __restrict__ val = (PASS == 0) ? g_s : g_t;
    float* __restrict__ acc = (PASS == 0) ? g_acc1 : g_acc2;
    int t = blockIdx.x * blockDim.x + threadIdx.x;
    int base = t * 8;
    if (base + 7 < e) {
        int4 sa = reinterpret_cast<const int4*>(src + base)[0];
        int4 sb = reinterpret_cast<const int4*>(src + base)[1];
        int4 da = reinterpret_cast<const int4*>(dst + base)[0];
        int4 db = reinterpret_cast<const int4*>(dst + base)[1];
        float v0 = __ldg(&val[sa.x]);
        float v1 = __ldg(&val[sa.y]);
        float v2 = __ldg(&val[sa.z]);
        float v3 = __ldg(&val[sa.w]);
        float v4 = __ldg(&val[sb.x]);
        float v5 = __ldg(&val[sb.y]);
        float v6 = __ldg(&val[sb.z]);
        float v7 = __ldg(&val[sb.w]);
        atomicAdd(&acc[da.x], v0);
        atomicAdd(&acc[da.y], v1);
        atomicAdd(&acc[da.z], v2);
        atomicAdd(&acc[da.w], v3);
        atomicAdd(&acc[db.x], v4);
        atomicAdd(&acc[db.y], v5);
        atomicAdd(&acc[db.z], v6);
        atomicAdd(&acc[db.w], v7);
    } else {
        for (int k = base; k < e; k++)
            atomicAdd(&acc[dst[k]], __ldg(&val[src[k]]));
    }
}

// ----------------------- node pass 2: layer1 epilogue + layer2 scalar, seed acc2
__global__ void k_node2(const float* __restrict__ W1, const float* __restrict__ b1,
                        const float* __restrict__ W2, int n) {
    int i = blockIdx.x * blockDim.x + threadIdx.x;
    if (i < n) {
        float dinv = g_dinv[i];
        float agg = dinv * g_acc1[i];
        float z = 0.0f;
#pragma unroll
        for (int f = 0; f < 16; f++) {
            float h = fmaf(agg, __ldg(&W1[f]), __ldg(&b1[f]));
            h = fmaxf(h, 0.0f);
            z = fmaf(h, __ldg(&W2[f]), z);
        }
        float tv = z * dinv;
        g_t[i] = tv;
        g_acc2[i] = tv;   // self loop
    }
}

// ----------------------------------------------------------- output pass
__global__ void k_out(float* __restrict__ out, const float* __restrict__ b2, int n) {
    int i = blockIdx.x * blockDim.x + threadIdx.x;
    if (i < n) {
        out[i] = fmaf(g_dinv[i], g_acc2[i], __ldg(&b2[0]));
    }
}

extern "C" void kernel_launch(void* const* d_in, const int* in_sizes, int n_in,
                              void* d_out, int out_size) {
    const float* x   = (const float*)d_in[0];
    const int*   ei  = (const int*)d_in[1];     // [2, E] int32 (downcast int64)
    const float* W1  = (const float*)d_in[2];
    const float* b1  = (const float*)d_in[3];
    const float* W2  = (const float*)d_in[4];
    const float* b2  = (const float*)d_in[5];
    float*       out = (float*)d_out;

    const int n = in_sizes[0];           // 200000
    const int e = in_sizes[1] / 2;       // 12800000
    const int* src = ei;
    const int* dst = ei + e;

    const int TB = 256;
    const int nblk = (n + TB - 1) / TB;
    const int groups = (e + 7) / 8;               // 8 edges per thread
    const int eblk = (groups + TB - 1) / TB;

    k_zero_deg<<<nblk, TB>>>(n);
    k_deg<<<eblk, TB>>>(dst, e);
    k_node1<<<nblk, TB>>>(x, n);
    k_edge<0><<<eblk, TB>>>(src, dst, e);
    k_node2<<<nblk, TB>>>(W1, b1, W2, n);
    k_edge<1><<<eblk, TB>>>(src, dst, e);
    k_out<<<nblk, TB>>>(out, b2, n);
}